// round 14
// baseline (speedup 1.0000x reference)
#include <cuda_runtime.h>
#include <cuda_bf16.h>
#include <cstdint>

// Problem constants (B=256, N=128, D=512)
#define BN    32768
#define DIM   512

// ---------------- device scratch (no allocations allowed) ----------------
__device__ __nv_bfloat16 g_xb[BN * DIM];     // bf16 copy of x, row-major (33.5MB, L2-resident)
__device__ float  g_E[DIM * DIM];            // E = 0.5*diag(r) - V V^T (plain stores, no zeroing)
__device__ double g_S;                       // interaction scalar accumulator

__device__ const int c_mt[10] = {0,0,0,0,1,1,1,2,2,3};
__device__ const int c_nt[10] = {0,1,2,3,1,2,3,2,3,3};

// ---------------- helpers ----------------
__device__ __forceinline__ unsigned smem_u32(const void* p) {
    return (unsigned)__cvta_generic_to_shared(p);
}
__device__ __forceinline__ unsigned pack_bf16x2(float a, float b) {
    __nv_bfloat162 h = __floats2bfloat162_rn(a, b);
    return *reinterpret_cast<unsigned*>(&h);
}
__device__ __forceinline__ void ldsm4t(unsigned* r, unsigned addr) {
    asm volatile("ldmatrix.sync.aligned.m8n8.x4.trans.shared.b16 {%0,%1,%2,%3}, [%4];"
                 : "=r"(r[0]), "=r"(r[1]), "=r"(r[2]), "=r"(r[3])
                 : "r"(addr));
}
__device__ __forceinline__ void mma16816(float* c, const unsigned* a, unsigned b0, unsigned b1) {
    asm volatile(
        "mma.sync.aligned.m16n8k16.row.col.f32.bf16.bf16.f32 "
        "{%0,%1,%2,%3}, {%4,%5,%6,%7}, {%8,%9}, {%0,%1,%2,%3};"
        : "+f"(c[0]), "+f"(c[1]), "+f"(c[2]), "+f"(c[3])
        : "r"(a[0]), "r"(a[1]), "r"(a[2]), "r"(a[3]), "r"(b0), "r"(b1));
}
__device__ __forceinline__ void cpasync16(unsigned saddr, const void* g) {
    asm volatile("cp.async.cg.shared.global [%0], [%1], 16;" :: "r"(saddr), "l"(g));
}
__device__ __forceinline__ void cp_commit() {
    asm volatile("cp.async.commit_group;");
}
template <int N>
__device__ __forceinline__ void cp_wait() {
    asm volatile("cp.async.wait_group %0;" :: "n"(N));
}

// ---------------- K1: merged prep ---------------------------------------
// blocks [0,256):   E output-split: tile(64x64) x 4 row-splits of 16 rows,
//                   FULL e-range -> plain float4 stores (no atomics/zeroing)
// blocks [256,2304): linear part + bf16 conversion (16 rows per block, R6 form)
__global__ __launch_bounds__(256) void k_prep(const float* __restrict__ x,
                                              const float* __restrict__ W,
                                              const float* __restrict__ bias,
                                              const float* __restrict__ V,
                                              float* __restrict__ out) {
    __shared__ float sVa[32 * 17];   // [e-chunk 32][16 rows + 1 pad]
    __shared__ float sVb[32 * 68];   // [e-chunk 32][64 rows + 4 pad]
    const int tid = threadIdx.x;
    const int blk = blockIdx.x;

    if (blk < 256) {
        // ---------- E block: rows di..di+16, cols dj..dj+64, e in [0,512) ----------
        if (blk == 0 && tid == 0) g_S = 0.0;
        const int tile = blk >> 2, q = blk & 3;
        const int di = (tile >> 3) * 64 + q * 16;
        const int dj = (tile & 7) * 64;
        const int tr = tid >> 4, tc = tid & 15;

        float acc[4] = {0.f, 0.f, 0.f, 0.f};

        for (int ch = 0; ch < 16; ch++) {          // 16 chunks of 32 e-values
            __syncthreads();
#pragma unroll
            for (int i = 0; i < 2; i++) {          // sVa: 512 floats
                int id2 = tid + i * 256;
                int rr = id2 & 15, cc = id2 >> 4;
                sVa[cc * 17 + rr] = V[(size_t)(di + rr) * DIM + ch * 32 + cc];
            }
#pragma unroll
            for (int i = 0; i < 8; i++) {          // sVb: 2048 floats
                int id2 = tid + i * 256;
                int rr = id2 & 63, cc = id2 >> 6;
                sVb[cc * 68 + rr] = V[(size_t)(dj + rr) * DIM + ch * 32 + cc];
            }
            __syncthreads();
#pragma unroll 8
            for (int ec = 0; ec < 32; ec++) {
                float a = sVa[ec * 17 + tr];
                float4 b = *reinterpret_cast<const float4*>(&sVb[ec * 68 + 4 * tc]);
                acc[0] += a * b.x; acc[1] += a * b.y;
                acc[2] += a * b.z; acc[3] += a * b.w;
            }
        }
        // E = 0.5*diag(r) - C ; diagonal: E_dd = -0.5*C_dd
        const int row = di + tr;
        float ev[4];
#pragma unroll
        for (int j = 0; j < 4; j++) {
            int col = dj + 4 * tc + j;
            ev[j] = (row == col) ? (-0.5f * acc[j]) : (-acc[j]);
        }
        float4 e = {ev[0], ev[1], ev[2], ev[3]};
        *reinterpret_cast<float4*>(&g_E[(size_t)row * DIM + dj + 4 * tc]) = e;
    } else {
        // ---------- linear + bf16 convert : 16 rows per CTA (R6 form) ----------
        float* sW = sVb;   // reuse smem
        for (int i = tid; i < DIM; i += 256) sW[i] = W[i];
        __syncthreads();

        const int warp = tid >> 5, lane = tid & 31;
        const int rbase = (blk - 256) * 16 + warp * 2;   // 2048 blocks * 16 rows
        const float4* wr = reinterpret_cast<const float4*>(sW);
        const float4 w0 = wr[2 * lane],      w1 = wr[2 * lane + 1];
        const float4 w2 = wr[64 + 2 * lane], w3 = wr[64 + 2 * lane + 1];

#pragma unroll
        for (int r = 0; r < 2; r++) {
            const int row = rbase + r;
            const float4* xr = reinterpret_cast<const float4*>(x + (size_t)row * DIM);
            uint4* xbr = reinterpret_cast<uint4*>(g_xb + (size_t)row * DIM);
            float4 a0 = xr[2 * lane], a1 = xr[2 * lane + 1];
            float4 a2 = xr[64 + 2 * lane], a3 = xr[64 + 2 * lane + 1];

            uint4 p0, p1;
            p0.x = pack_bf16x2(a0.x, a0.y); p0.y = pack_bf16x2(a0.z, a0.w);
            p0.z = pack_bf16x2(a1.x, a1.y); p0.w = pack_bf16x2(a1.z, a1.w);
            p1.x = pack_bf16x2(a2.x, a2.y); p1.y = pack_bf16x2(a2.z, a2.w);
            p1.z = pack_bf16x2(a3.x, a3.y); p1.w = pack_bf16x2(a3.z, a3.w);
            xbr[lane] = p0;
            xbr[32 + lane] = p1;

            float s0 = a0.x * w0.x + a0.y * w0.y + a0.z * w0.z + a0.w * w0.w;
            float s1 = a1.x * w1.x + a1.y * w1.y + a1.z * w1.z + a1.w * w1.w;
            float s2 = a2.x * w2.x + a2.y * w2.y + a2.z * w2.z + a2.w * w2.w;
            float s3 = a3.x * w3.x + a3.y * w3.y + a3.z * w3.z + a3.w * w3.w;
            float s = (s0 + s1) + (s2 + s3);
#pragma unroll
            for (int off = 16; off; off >>= 1) s += __shfl_xor_sync(0xffffffffu, s, off);
            if (lane == 0) out[row] = s + bias[0];
        }
    }
}

// ---------------- K2: Gram tiles — 4-stage cp.async pipeline (R10 form) --
// 10 upper-triangular 128x128 tiles x 28 k-splits = 280 CTAs (2 per SM).
// TKB=16 rows/stage, 4 buffers, loads 3 stages ahead, one sync per stage.
// Epilogue: dot with SINGLE g_E; plain atomic into g_S (no broadcast).
#define TKB 16
#define LDP 136           // bf16 pitch: 272B row stride -> conflict-free ldsm
#define NSTG 4
#define NSPLIT 28
#define NBLK  (10 * NSPLIT)
#define NCHUNK (BN / TKB) // 2048

__global__ __launch_bounds__(256, 2) void k_gram() {
    __shared__ __align__(16) __nv_bfloat16 sA[NSTG][TKB * LDP];
    __shared__ __align__(16) __nv_bfloat16 sB[NSTG][TKB * LDP];
    __shared__ float red[256];

    const int tid  = threadIdx.x;
    const int bid  = blockIdx.x;
    const int tile = bid % 10;
    const int ks   = bid / 10;
    const int mt = c_mt[tile], nt = c_nt[tile];
    const bool diag = (mt == nt);
    const int m0 = mt * 128, n0 = nt * 128;
    const int ch0 = (ks * NCHUNK) / NSPLIT;
    const int ch1 = ((ks + 1) * NCHUNK) / NSPLIT;
    const int k0  = ch0 * TKB;
    const int nst = ch1 - ch0;            // 73 or 74 stages

    const int lane = tid & 31, warp = tid >> 5;
    const int wm0 = (warp >> 2) * 64;
    const int wn0 = (warp & 3) * 32;

    // ldmatrix lane mapping
    const int sub = lane >> 3, r8 = lane & 7;
    const int lmk = r8 + ((sub >> 1) << 3);
    const int lmc = (sub & 1) << 3;
    const unsigned lmoff = (unsigned)((lmk * LDP + lmc) * 2);

    // cp.async mapping: 256 16B-chunks per buffer; 1 per thread per matrix.
    const int rc = tid >> 4, cc16 = tid & 15;
    const unsigned soff = (unsigned)(rc * (LDP * 2) + cc16 * 16);
    const char* gA = (const char*)(g_xb + (size_t)(k0 + rc) * DIM + m0) + cc16 * 16;
    const char* gB = (const char*)(g_xb + (size_t)(k0 + rc) * DIM + n0) + cc16 * 16;
    unsigned sAb[NSTG], sBb[NSTG];
#pragma unroll
    for (int i = 0; i < NSTG; i++) {
        sAb[i] = smem_u32(&sA[i][0]);
        sBb[i] = smem_u32(&sB[i][0]);
    }

    auto issue = [&](int s) {
        const int buf = s & (NSTG - 1);
        const size_t go = (size_t)s * (TKB * DIM * 2);
        cpasync16(sAb[buf] + soff, gA + go);
        if (!diag) cpasync16(sBb[buf] + soff, gB + go);
        cp_commit();
    };

    float acc[4][4][4];
#pragma unroll
    for (int i = 0; i < 4; i++)
#pragma unroll
        for (int j = 0; j < 4; j++)
#pragma unroll
            for (int q = 0; q < 4; q++) acc[i][j][q] = 0.f;

    issue(0); issue(1); issue(2);

    for (int s = 0; s < nst; s++) {
        const int buf = s & (NSTG - 1);
        if (s + 2 < nst)      cp_wait<2>();
        else if (s + 1 < nst) cp_wait<1>();
        else                  cp_wait<0>();
        __syncthreads();   // buffer s visible; all threads done with buffer s-1

        const unsigned baseA = sAb[buf] + lmoff;
        const unsigned baseB = (diag ? sAb[buf] : sBb[buf]) + lmoff;
        unsigned afr[4][4];
#pragma unroll
        for (int mi = 0; mi < 4; mi++)
            ldsm4t(afr[mi], baseA + (unsigned)((wm0 + mi * 16) * 2));
        unsigned bq[2][4];
#pragma unroll
        for (int nb = 0; nb < 2; nb++)
            ldsm4t(bq[nb], baseB + (unsigned)((wn0 + nb * 16) * 2));
#pragma unroll
        for (int mi = 0; mi < 4; mi++) {
            mma16816(acc[mi][0], afr[mi], bq[0][0], bq[0][2]);
            mma16816(acc[mi][1], afr[mi], bq[0][1], bq[0][3]);
            mma16816(acc[mi][2], afr[mi], bq[1][0], bq[1][2]);
            mma16816(acc[mi][3], afr[mi], bq[1][1], bq[1][3]);
        }

        if (s + 3 < nst) issue(s + 3);
    }

    // ---- fused trace epilogue: partial = sum(acc .* E_tile), single g_E ----
    const int g = lane >> 2, t4 = lane & 3;
    float fsum = 0.f;
#pragma unroll
    for (int mi = 0; mi < 4; mi++) {
#pragma unroll
        for (int ni = 0; ni < 4; ni++) {
            int row0 = m0 + wm0 + mi * 16 + g;
            int col0 = n0 + wn0 + ni * 8 + 2 * t4;
            float2 e0 = *reinterpret_cast<const float2*>(&g_E[(size_t)row0 * DIM + col0]);
            float2 e1 = *reinterpret_cast<const float2*>(&g_E[(size_t)(row0 + 8) * DIM + col0]);
            fsum += acc[mi][ni][0] * e0.x + acc[mi][ni][1] * e0.y
                  + acc[mi][ni][2] * e1.x + acc[mi][ni][3] * e1.y;
        }
    }
    red[tid] = fsum;
    __syncthreads();
    for (int o = 128; o; o >>= 1) {
        if (tid < o) red[tid] += red[tid + o];
        __syncthreads();
    }
    if (tid == 0) {
        double w = diag ? 1.0 : 2.0;   // symmetry: off-diagonal tiles counted twice
        atomicAdd(&g_S, w * (double)red[0]);
    }
}

// ---------------- K3: broadcast-add the interaction scalar ----------------
__global__ void k_final(float* __restrict__ out) {
    int i = blockIdx.x * 256 + threadIdx.x;       // 128 blocks
    out[i] += (float)g_S;
}

// ---------------- launch ----------------
extern "C" void kernel_launch(void* const* d_in, const int* in_sizes, int n_in,
                              void* d_out, int out_size) {
    const float* x = (const float*)d_in[0];   // [256,128,512]
    const float* W = (const float*)d_in[1];   // [1,512]
    const float* b = (const float*)d_in[2];   // [1]
    const float* V = (const float*)d_in[3];   // [512,512]
    float* out = (float*)d_out;               // [32768,1]

    k_prep <<<256 + BN / 16, 256>>>(x, W, b, V, out);
    k_gram <<<NBLK, 256>>>();
    k_final<<<BN / 256, 256>>>(out);
}

// round 15
// speedup vs baseline: 1.2782x; 1.2782x over previous
#include <cuda_runtime.h>
#include <cuda_bf16.h>
#include <cstdint>

// Problem constants (B=256, N=128, D=512)
#define BN    32768
#define DIM   512

// ---------------- device scratch (no allocations allowed) ----------------
__device__ __nv_bfloat16 g_xb[BN * DIM];     // bf16 copy of x, row-major
__device__ float  g_E[DIM * DIM];            // E = 0.5*diag(r) - V V^T
__device__ double g_S;                       // interaction scalar accumulator
__device__ unsigned g_chunkcnt[512];         // per-64-row chunk completion counters
__device__ unsigned g_ecnt;                  // E-block completion counter

__device__ const int c_mt[10] = {0,0,0,0,1,1,1,2,2,3};
__device__ const int c_nt[10] = {0,1,2,3,1,2,3,2,3,3};

// ---------------- helpers ----------------
__device__ __forceinline__ unsigned smem_u32(const void* p) {
    return (unsigned)__cvta_generic_to_shared(p);
}
__device__ __forceinline__ unsigned pack_bf16x2(float a, float b) {
    __nv_bfloat162 h = __floats2bfloat162_rn(a, b);
    return *reinterpret_cast<unsigned*>(&h);
}
__device__ __forceinline__ void ldsm4t(unsigned* r, unsigned addr) {
    asm volatile("ldmatrix.sync.aligned.m8n8.x4.trans.shared.b16 {%0,%1,%2,%3}, [%4];"
                 : "=r"(r[0]), "=r"(r[1]), "=r"(r[2]), "=r"(r[3])
                 : "r"(addr));
}
__device__ __forceinline__ void mma16816(float* c, const unsigned* a, unsigned b0, unsigned b1) {
    asm volatile(
        "mma.sync.aligned.m16n8k16.row.col.f32.bf16.bf16.f32 "
        "{%0,%1,%2,%3}, {%4,%5,%6,%7}, {%8,%9}, {%0,%1,%2,%3};"
        : "+f"(c[0]), "+f"(c[1]), "+f"(c[2]), "+f"(c[3])
        : "r"(a[0]), "r"(a[1]), "r"(a[2]), "r"(a[3]), "r"(b0), "r"(b1));
}
__device__ __forceinline__ void cpasync16(unsigned saddr, const void* g) {
    asm volatile("cp.async.cg.shared.global [%0], [%1], 16;" :: "r"(saddr), "l"(g));
}
__device__ __forceinline__ void cp_commit() {
    asm volatile("cp.async.commit_group;");
}
template <int N>
__device__ __forceinline__ void cp_wait() {
    asm volatile("cp.async.wait_group %0;" :: "n"(N));
}

// ---------------- fused kernel: gram consumers + prep producers ----------
#define LDP   136                 // bf16 pitch: 272B rows, conflict-free ldsm
#define TILEB (16 * LDP * 2)      // 4352 B per 16-k tile
#define NSTG  8                   // 8 buffers = 2 chunks in flight
#define NSPLIT 14
#define GRAM_BLKS (10 * NSPLIT)   // 140 (< 148 -> producers always schedulable)
#define LIN_BLKS  2048
#define E_BLKS    256
#define TOT_BLKS  (GRAM_BLKS + LIN_BLKS + E_BLKS)
#define DSMEM (NSTG * TILEB * 2)  // 69632 B

__global__ __launch_bounds__(256, 2) void k_fused(const float* __restrict__ x,
                                                  const float* __restrict__ W,
                                                  const float* __restrict__ bias,
                                                  const float* __restrict__ V,
                                                  float* __restrict__ out) {
    extern __shared__ __align__(16) unsigned char dsm[];
    __shared__ float red[256];
    const int tid = threadIdx.x;
    const int bid = blockIdx.x;

    if (bid < GRAM_BLKS) {
        // ================= GRAM consumer =================
        const int tile = bid % 10, ks = bid / 10;
        const int mt = c_mt[tile], nt = c_nt[tile];
        const bool diag = (mt == nt);
        const int m0 = mt * 128, n0 = nt * 128;
        const int nch = (512 - ks + NSPLIT - 1) / NSPLIT;   // 36 or 37 chunks

        const int lane = tid & 31, warp = tid >> 5;
        const int wm0 = (warp >> 2) * 64;
        const int wn0 = (warp & 3) * 32;
        const int sub = lane >> 3, r8 = lane & 7;
        const int lmk = r8 + ((sub >> 1) << 3);
        const int lmc = (sub & 1) << 3;
        const unsigned lmoff = (unsigned)((lmk * LDP + lmc) * 2);

        const int rc = tid >> 4, cc16 = tid & 15;
        const unsigned soff = (unsigned)(rc * (LDP * 2) + cc16 * 16);
        const unsigned dA = smem_u32(dsm);
        const unsigned dB = dA + NSTG * TILEB;

        auto wait_chunk = [&](int c) {
            if (tid == 0) {
                while (atomicAdd(&g_chunkcnt[c], 0u) < 4u) {}
            }
            __syncthreads();      // also the buffer-reuse barrier
            __threadfence();
        };
        auto issue4 = [&](int jj) {
            const int c = ks + NSPLIT * jj;
#pragma unroll
            for (int s = 0; s < 4; s++) {
                const int buf = (4 * jj + s) & (NSTG - 1);
                const size_t krow = (size_t)(64 * c + 16 * s + rc);
                const char* srcA = (const char*)(g_xb + krow * DIM + m0) + cc16 * 16;
                cpasync16(dA + buf * TILEB + soff, srcA);
                if (!diag) cpasync16(dB + buf * TILEB + soff, srcA + (n0 - m0) * 2);
                cp_commit();
            }
        };

        float acc[4][4][4];
#pragma unroll
        for (int i = 0; i < 4; i++)
#pragma unroll
            for (int j = 0; j < 4; j++)
#pragma unroll
                for (int q = 0; q < 4; q++) acc[i][j][q] = 0.f;

        auto stage_mma = [&](int buf) {
            const unsigned baseA = dA + buf * TILEB + lmoff;
            const unsigned baseB = (diag ? dA : dB) + buf * TILEB + lmoff;
            unsigned afr[4][4];
#pragma unroll
            for (int mi = 0; mi < 4; mi++)
                ldsm4t(afr[mi], baseA + (unsigned)((wm0 + mi * 16) * 2));
            unsigned bq[2][4];
#pragma unroll
            for (int nb = 0; nb < 2; nb++)
                ldsm4t(bq[nb], baseB + (unsigned)((wn0 + nb * 16) * 2));
#pragma unroll
            for (int mi = 0; mi < 4; mi++) {
                mma16816(acc[mi][0], afr[mi], bq[0][0], bq[0][2]);
                mma16816(acc[mi][1], afr[mi], bq[0][1], bq[0][3]);
                mma16816(acc[mi][2], afr[mi], bq[1][0], bq[1][2]);
                mma16816(acc[mi][3], afr[mi], bq[1][1], bq[1][3]);
            }
        };

        wait_chunk(ks);
        issue4(0);
        for (int j = 0; j < nch; j++) {
            if (j + 1 < nch) {
                wait_chunk(ks + NSPLIT * (j + 1));   // sync also fences buffer reuse
                issue4(j + 1);
                cp_wait<7>(); __syncthreads(); stage_mma((4 * j + 0) & 7);
                cp_wait<6>(); __syncthreads(); stage_mma((4 * j + 1) & 7);
                cp_wait<5>(); __syncthreads(); stage_mma((4 * j + 2) & 7);
                cp_wait<4>(); __syncthreads(); stage_mma((4 * j + 3) & 7);
            } else {
                cp_wait<3>(); __syncthreads(); stage_mma((4 * j + 0) & 7);
                cp_wait<2>(); __syncthreads(); stage_mma((4 * j + 1) & 7);
                cp_wait<1>(); __syncthreads(); stage_mma((4 * j + 2) & 7);
                cp_wait<0>(); __syncthreads(); stage_mma((4 * j + 3) & 7);
            }
        }

        // wait for E to be fully written, then fused trace epilogue
        if (tid == 0) {
            while (atomicAdd(&g_ecnt, 0u) < (unsigned)E_BLKS) {}
        }
        __syncthreads();
        __threadfence();

        const int g = lane >> 2, t4 = lane & 3;
        float fsum = 0.f;
#pragma unroll
        for (int mi = 0; mi < 4; mi++) {
#pragma unroll
            for (int ni = 0; ni < 4; ni++) {
                int row0 = m0 + wm0 + mi * 16 + g;
                int col0 = n0 + wn0 + ni * 8 + 2 * t4;
                float2 e0 = *reinterpret_cast<const float2*>(&g_E[(size_t)row0 * DIM + col0]);
                float2 e1 = *reinterpret_cast<const float2*>(&g_E[(size_t)(row0 + 8) * DIM + col0]);
                fsum += acc[mi][ni][0] * e0.x + acc[mi][ni][1] * e0.y
                      + acc[mi][ni][2] * e1.x + acc[mi][ni][3] * e1.y;
            }
        }
        red[tid] = fsum;
        __syncthreads();
        for (int o = 128; o; o >>= 1) {
            if (tid < o) red[tid] += red[tid + o];
            __syncthreads();
        }
        if (tid == 0) {
            double w = diag ? 1.0 : 2.0;
            atomicAdd(&g_S, w * (double)red[0]);
        }
    } else if (bid < GRAM_BLKS + LIN_BLKS) {
        // ================= linear + bf16 producer (R6 form) =================
        float* sW = reinterpret_cast<float*>(dsm);
        for (int i = tid; i < DIM; i += 256) sW[i] = W[i];
        __syncthreads();

        const int lb = bid - GRAM_BLKS;
        const int warp = tid >> 5, lane = tid & 31;
        const int rbase = lb * 16 + warp * 2;
        const float4* wr = reinterpret_cast<const float4*>(sW);
        const float4 w0 = wr[2 * lane],      w1 = wr[2 * lane + 1];
        const float4 w2 = wr[64 + 2 * lane], w3 = wr[64 + 2 * lane + 1];

#pragma unroll
        for (int r = 0; r < 2; r++) {
            const int row = rbase + r;
            const float4* xr = reinterpret_cast<const float4*>(x + (size_t)row * DIM);
            uint4* xbr = reinterpret_cast<uint4*>(g_xb + (size_t)row * DIM);
            float4 a0 = xr[2 * lane], a1 = xr[2 * lane + 1];
            float4 a2 = xr[64 + 2 * lane], a3 = xr[64 + 2 * lane + 1];

            uint4 p0, p1;
            p0.x = pack_bf16x2(a0.x, a0.y); p0.y = pack_bf16x2(a0.z, a0.w);
            p0.z = pack_bf16x2(a1.x, a1.y); p0.w = pack_bf16x2(a1.z, a1.w);
            p1.x = pack_bf16x2(a2.x, a2.y); p1.y = pack_bf16x2(a2.z, a2.w);
            p1.z = pack_bf16x2(a3.x, a3.y); p1.w = pack_bf16x2(a3.z, a3.w);
            xbr[lane] = p0;
            xbr[32 + lane] = p1;

            float s0 = a0.x * w0.x + a0.y * w0.y + a0.z * w0.z + a0.w * w0.w;
            float s1 = a1.x * w1.x + a1.y * w1.y + a1.z * w1.z + a1.w * w1.w;
            float s2 = a2.x * w2.x + a2.y * w2.y + a2.z * w2.z + a2.w * w2.w;
            float s3 = a3.x * w3.x + a3.y * w3.y + a3.z * w3.z + a3.w * w3.w;
            float s = (s0 + s1) + (s2 + s3);
#pragma unroll
            for (int off = 16; off; off >>= 1) s += __shfl_xor_sync(0xffffffffu, s, off);
            if (lane == 0) out[row] = s + bias[0];
        }
        __syncthreads();
        __threadfence();
        if (tid == 0) atomicAdd(&g_chunkcnt[lb >> 2], 1u);   // chunk = 64 rows = 4 CTAs
    } else {
        // ================= E producer (coalesced; output-split) =================
        float* sVa = reinterpret_cast<float*>(dsm);           // [32 e][16 rows +1]
        float* sVb = sVa + 32 * 17;                           // [32 e][64 rows +4]
        const int eb = bid - GRAM_BLKS - LIN_BLKS;
        const int tile = eb >> 2, q = eb & 3;
        const int di = (tile >> 3) * 64 + q * 16;
        const int dj = (tile & 7) * 64;
        const int tr = tid >> 4, tc = tid & 15;

        float acc[4] = {0.f, 0.f, 0.f, 0.f};
        for (int ch = 0; ch < 16; ch++) {
            __syncthreads();
#pragma unroll
            for (int i = 0; i < 2; i++) {                     // sVa: 512 floats
                int id2 = tid + i * 256;
                int cc = id2 & 31, rr = id2 >> 5;             // cc along e: coalesced
                sVa[cc * 17 + rr] = V[(size_t)(di + rr) * DIM + ch * 32 + cc];
            }
#pragma unroll
            for (int i = 0; i < 8; i++) {                     // sVb: 2048 floats
                int id2 = tid + i * 256;
                int cc = id2 & 31, rr = id2 >> 5;             // rr 0..63
                sVb[cc * 68 + rr] = V[(size_t)(dj + rr) * DIM + ch * 32 + cc];
            }
            __syncthreads();
#pragma unroll 8
            for (int ec = 0; ec < 32; ec++) {
                float a = sVa[ec * 17 + tr];
                float4 b = *reinterpret_cast<const float4*>(&sVb[ec * 68 + 4 * tc]);
                acc[0] += a * b.x; acc[1] += a * b.y;
                acc[2] += a * b.z; acc[3] += a * b.w;
            }
        }
        const int row = di + tr;
        float ev[4];
#pragma unroll
        for (int j = 0; j < 4; j++) {
            int col = dj + 4 * tc + j;
            ev[j] = (row == col) ? (-0.5f * acc[j]) : (-acc[j]);
        }
        float4 e = {ev[0], ev[1], ev[2], ev[3]};
        *reinterpret_cast<float4*>(&g_E[(size_t)row * DIM + dj + 4 * tc]) = e;
        __syncthreads();
        __threadfence();
        if (tid == 0) atomicAdd(&g_ecnt, 1u);
    }
}

// ---------------- K2: broadcast-add + reset counters ---------------------
__global__ void k_final(float* __restrict__ out) {
    int i = blockIdx.x * 256 + threadIdx.x;       // 128 blocks
    out[i] += (float)g_S;
    if (blockIdx.x == 0) {                        // safe: k_fused finished
        g_chunkcnt[threadIdx.x] = 0u;
        g_chunkcnt[threadIdx.x + 256] = 0u;
        if (threadIdx.x == 0) g_ecnt = 0u;
    }
}

// ---------------- K3: reset g_S (cannot race k_final's readers) ----------
__global__ void k_resetS() {
    g_S = 0.0;
}

// ---------------- launch ----------------
extern "C" void kernel_launch(void* const* d_in, const int* in_sizes, int n_in,
                              void* d_out, int out_size) {
    const float* x = (const float*)d_in[0];   // [256,128,512]
    const float* W = (const float*)d_in[1];   // [1,512]
    const float* b = (const float*)d_in[2];   // [1]
    const float* V = (const float*)d_in[3];   // [512,512]
    float* out = (float*)d_out;               // [32768,1]

    cudaFuncSetAttribute(k_fused, cudaFuncAttributeMaxDynamicSharedMemorySize, DSMEM);
    k_fused <<<TOT_BLKS, 256, DSMEM>>>(x, W, b, V, out);
    k_final <<<BN / 256, 256>>>(out);
    k_resetS<<<1, 1>>>();
}

// round 16
// speedup vs baseline: 2.0280x; 1.5866x over previous
#include <cuda_runtime.h>
#include <cuda_bf16.h>
#include <cstdint>

// Problem constants (B=256, N=128, D=512)
#define BN    32768
#define DIM   512

// ---------------- device scratch (no allocations allowed) ----------------
__device__ __nv_bfloat16 g_xb[BN * DIM];   // bf16 copy of x (33.5 MB, fits L2)
__device__ float  g_E[DIM * DIM];          // E = 0.5*diag(r) - V V^T, fp32
__device__ double g_S;                     // sum G .* E  (the interaction scalar)

__device__ const int c_mt[10] = {0,0,0,0,1,1,1,2,2,3};
__device__ const int c_nt[10] = {0,1,2,3,1,2,3,2,3,3};

// ---------------- helpers ----------------
__device__ __forceinline__ unsigned smem_u32(const void* p) {
    return (unsigned)__cvta_generic_to_shared(p);
}
__device__ __forceinline__ unsigned pack_bf16x2(float a, float b) {
    __nv_bfloat162 h = __floats2bfloat162_rn(a, b);
    return *reinterpret_cast<unsigned*>(&h);
}
__device__ __forceinline__ void ldsm4t(unsigned* r, unsigned addr) {
    asm volatile("ldmatrix.sync.aligned.m8n8.x4.trans.shared.b16 {%0,%1,%2,%3}, [%4];"
                 : "=r"(r[0]), "=r"(r[1]), "=r"(r[2]), "=r"(r[3])
                 : "r"(addr));
}
__device__ __forceinline__ void mma16816(float* c, const unsigned* a, unsigned b0, unsigned b1) {
    asm volatile(
        "mma.sync.aligned.m16n8k16.row.col.f32.bf16.bf16.f32 "
        "{%0,%1,%2,%3}, {%4,%5,%6,%7}, {%8,%9}, {%0,%1,%2,%3};"
        : "+f"(c[0]), "+f"(c[1]), "+f"(c[2]), "+f"(c[3])
        : "r"(a[0]), "r"(a[1]), "r"(a[2]), "r"(a[3]), "r"(b0), "r"(b1));
}
__device__ __forceinline__ void cpasync16(unsigned saddr, const void* g) {
    asm volatile("cp.async.cg.shared.global [%0], [%1], 16;" :: "r"(saddr), "l"(g));
}
__device__ __forceinline__ void cp_commit() {
    asm volatile("cp.async.commit_group;");
}
template <int N>
__device__ __forceinline__ void cp_wait() {
    asm volatile("cp.async.wait_group %0;" :: "n"(N));
}

// ---------------- K0: zero g_E + g_S (R6 form) ----------------
__global__ void k_zero() {
    int idx = blockIdx.x * 256 + threadIdx.x;      // 64 CTAs -> 16384 threads
    float4 z = {0.f, 0.f, 0.f, 0.f};
#pragma unroll
    for (int i = 0; i < 4; i++)
        reinterpret_cast<float4*>(g_E)[idx + i * 16384] = z;
    if (idx == 0) g_S = 0.0;
}

// ---------------- K1: merged prep (R6 form, 73.2us-measured) -------------
// blocks [0,256):   E partials (64 tiles x 4 e-splits) atomically into g_E
// blocks [256,2304): linear part + bf16 conversion (16 rows per block)
__global__ __launch_bounds__(256) void k_prep(const float* __restrict__ x,
                                              const float* __restrict__ W,
                                              const float* __restrict__ bias,
                                              const float* __restrict__ V,
                                              float* __restrict__ out) {
    __shared__ float sVa[32 * 68];
    __shared__ float sVb[32 * 68];
    const int tid = threadIdx.x;
    const int blk = blockIdx.x;

    if (blk < 256) {
        // ---------- E tile partial (e-range of 128) ----------
        const int tile = blk >> 2, es = blk & 3;
        const int di = (tile >> 3) * 64, dj = (tile & 7) * 64;
        const int e0 = es * 128;
        const int tr = tid >> 4, tc = tid & 15;

        float acc[4][4];
#pragma unroll
        for (int i = 0; i < 4; i++)
#pragma unroll
            for (int j = 0; j < 4; j++) acc[i][j] = 0.f;

        for (int ch = 0; ch < 4; ch++) {           // 4 chunks of 32 e-values
            __syncthreads();
#pragma unroll
            for (int i = 0; i < 8; i++) {
                int idx = tid + i * 256;
                int rr = idx >> 5, cc = idx & 31;
                sVa[cc * 68 + rr] = V[(size_t)(di + rr) * DIM + e0 + ch * 32 + cc];
                sVb[cc * 68 + rr] = V[(size_t)(dj + rr) * DIM + e0 + ch * 32 + cc];
            }
            __syncthreads();
#pragma unroll 4
            for (int ec = 0; ec < 32; ec++) {
                float4 av = reinterpret_cast<const float4*>(sVa)[ec * 17 + tr];
                float4 bv = reinterpret_cast<const float4*>(sVb)[ec * 17 + tc];
                float a4[4] = {av.x, av.y, av.z, av.w};
                float b4[4] = {bv.x, bv.y, bv.z, bv.w};
#pragma unroll
                for (int i = 0; i < 4; i++)
#pragma unroll
                    for (int j = 0; j < 4; j++) acc[i][j] += a4[i] * b4[j];
            }
        }
        // E = 0.5*diag(r) - C ; on diagonal the partial is -0.5*c
#pragma unroll
        for (int i = 0; i < 4; i++) {
            int row = di + tr * 4 + i;
#pragma unroll
            for (int j = 0; j < 4; j++) {
                int col = dj + tc * 4 + j;
                float c = acc[i][j];
                float e = (row == col) ? (-0.5f * c) : (-c);
                atomicAdd(&g_E[(size_t)row * DIM + col], e);
            }
        }
    } else {
        // ---------- linear + bf16 convert : 16 rows per CTA ----------
        float* sW = sVa;   // reuse smem
        for (int i = tid; i < DIM; i += 256) sW[i] = W[i];
        __syncthreads();

        const int warp = tid >> 5, lane = tid & 31;
        const int rbase = (blk - 256) * 16 + warp * 2;   // 2048 blocks * 16 rows
        const float4* wr = reinterpret_cast<const float4*>(sW);
        const float4 w0 = wr[2 * lane],      w1 = wr[2 * lane + 1];
        const float4 w2 = wr[64 + 2 * lane], w3 = wr[64 + 2 * lane + 1];

#pragma unroll
        for (int r = 0; r < 2; r++) {
            const int row = rbase + r;
            const float4* xr = reinterpret_cast<const float4*>(x + (size_t)row * DIM);
            uint4* xbr = reinterpret_cast<uint4*>(g_xb + (size_t)row * DIM);
            float4 a0 = xr[2 * lane], a1 = xr[2 * lane + 1];
            float4 a2 = xr[64 + 2 * lane], a3 = xr[64 + 2 * lane + 1];

            uint4 p0, p1;
            p0.x = pack_bf16x2(a0.x, a0.y); p0.y = pack_bf16x2(a0.z, a0.w);
            p0.z = pack_bf16x2(a1.x, a1.y); p0.w = pack_bf16x2(a1.z, a1.w);
            p1.x = pack_bf16x2(a2.x, a2.y); p1.y = pack_bf16x2(a2.z, a2.w);
            p1.z = pack_bf16x2(a3.x, a3.y); p1.w = pack_bf16x2(a3.z, a3.w);
            xbr[lane] = p0;
            xbr[32 + lane] = p1;

            float s0 = a0.x * w0.x + a0.y * w0.y + a0.z * w0.z + a0.w * w0.w;
            float s1 = a1.x * w1.x + a1.y * w1.y + a1.z * w1.z + a1.w * w1.w;
            float s2 = a2.x * w2.x + a2.y * w2.y + a2.z * w2.z + a2.w * w2.w;
            float s3 = a3.x * w3.x + a3.y * w3.y + a3.z * w3.z + a3.w * w3.w;
            float s = (s0 + s1) + (s2 + s3);
#pragma unroll
            for (int off = 16; off; off >>= 1) s += __shfl_xor_sync(0xffffffffu, s, off);
            if (lane == 0) out[row] = s + bias[0];
        }
    }
}

// ---------------- K2: Gram tiles — 4-stage cp.async pipeline (R10 form) --
// 10 upper-triangular 128x128 tiles x 28 k-splits = 280 CTAs (2 per SM).
// TKB=16 rows/stage, 4 buffers, loads 3 stages ahead, one sync per stage.
// Epilogue: dot with single g_E; plain atomic into g_S.
#define TKB 16
#define LDP 136           // bf16 pitch: 272B row stride -> conflict-free ldsm
#define NSTG 4
#define NSPLIT 28
#define NBLK  (10 * NSPLIT)
#define NCHUNK (BN / TKB) // 2048

__global__ __launch_bounds__(256, 2) void k_gram() {
    __shared__ __align__(16) __nv_bfloat16 sA[NSTG][TKB * LDP];
    __shared__ __align__(16) __nv_bfloat16 sB[NSTG][TKB * LDP];
    __shared__ float red[256];

    const int tid  = threadIdx.x;
    const int bid  = blockIdx.x;
    const int tile = bid % 10;
    const int ks   = bid / 10;
    const int mt = c_mt[tile], nt = c_nt[tile];
    const bool diag = (mt == nt);
    const int m0 = mt * 128, n0 = nt * 128;
    const int ch0 = (ks * NCHUNK) / NSPLIT;
    const int ch1 = ((ks + 1) * NCHUNK) / NSPLIT;
    const int k0  = ch0 * TKB;
    const int nst = ch1 - ch0;            // 73 or 74 stages

    const int lane = tid & 31, warp = tid >> 5;
    const int wm0 = (warp >> 2) * 64;
    const int wn0 = (warp & 3) * 32;

    // ldmatrix lane mapping
    const int sub = lane >> 3, r8 = lane & 7;
    const int lmk = r8 + ((sub >> 1) << 3);
    const int lmc = (sub & 1) << 3;
    const unsigned lmoff = (unsigned)((lmk * LDP + lmc) * 2);

    // cp.async mapping: 256 16B-chunks per buffer; 1 per thread per matrix.
    const int rc = tid >> 4, cc16 = tid & 15;
    const unsigned soff = (unsigned)(rc * (LDP * 2) + cc16 * 16);
    const char* gA = (const char*)(g_xb + (size_t)(k0 + rc) * DIM + m0) + cc16 * 16;
    const char* gB = (const char*)(g_xb + (size_t)(k0 + rc) * DIM + n0) + cc16 * 16;
    unsigned sAb[NSTG], sBb[NSTG];
#pragma unroll
    for (int i = 0; i < NSTG; i++) {
        sAb[i] = smem_u32(&sA[i][0]);
        sBb[i] = smem_u32(&sB[i][0]);
    }

    auto issue = [&](int s) {
        const int buf = s & (NSTG - 1);
        const size_t go = (size_t)s * (TKB * DIM * 2);
        cpasync16(sAb[buf] + soff, gA + go);
        if (!diag) cpasync16(sBb[buf] + soff, gB + go);
        cp_commit();
    };

    float acc[4][4][4];
#pragma unroll
    for (int i = 0; i < 4; i++)
#pragma unroll
        for (int j = 0; j < 4; j++)
#pragma unroll
            for (int q = 0; q < 4; q++) acc[i][j][q] = 0.f;

    issue(0); issue(1); issue(2);

    for (int s = 0; s < nst; s++) {
        const int buf = s & (NSTG - 1);
        if (s + 2 < nst)      cp_wait<2>();
        else if (s + 1 < nst) cp_wait<1>();
        else                  cp_wait<0>();
        __syncthreads();   // buffer s visible; all threads done with buffer s-1

        const unsigned baseA = sAb[buf] + lmoff;
        const unsigned baseB = (diag ? sAb[buf] : sBb[buf]) + lmoff;
        unsigned afr[4][4];
#pragma unroll
        for (int mi = 0; mi < 4; mi++)
            ldsm4t(afr[mi], baseA + (unsigned)((wm0 + mi * 16) * 2));
        unsigned bq[2][4];
#pragma unroll
        for (int nb = 0; nb < 2; nb++)
            ldsm4t(bq[nb], baseB + (unsigned)((wn0 + nb * 16) * 2));
#pragma unroll
        for (int mi = 0; mi < 4; mi++) {
            mma16816(acc[mi][0], afr[mi], bq[0][0], bq[0][2]);
            mma16816(acc[mi][1], afr[mi], bq[0][1], bq[0][3]);
            mma16816(acc[mi][2], afr[mi], bq[1][0], bq[1][2]);
            mma16816(acc[mi][3], afr[mi], bq[1][1], bq[1][3]);
        }

        if (s + 3 < nst) issue(s + 3);
    }

    // ---- fused trace epilogue: partial = sum(acc .* E_tile) ----
    const int g = lane >> 2, t4 = lane & 3;
    float fsum = 0.f;
#pragma unroll
    for (int mi = 0; mi < 4; mi++) {
#pragma unroll
        for (int ni = 0; ni < 4; ni++) {
            int row0 = m0 + wm0 + mi * 16 + g;
            int col0 = n0 + wn0 + ni * 8 + 2 * t4;
            float2 e0 = *reinterpret_cast<const float2*>(&g_E[(size_t)row0 * DIM + col0]);
            float2 e1 = *reinterpret_cast<const float2*>(&g_E[(size_t)(row0 + 8) * DIM + col0]);
            fsum += acc[mi][ni][0] * e0.x + acc[mi][ni][1] * e0.y
                  + acc[mi][ni][2] * e1.x + acc[mi][ni][3] * e1.y;
        }
    }
    red[tid] = fsum;
    __syncthreads();
    for (int o = 128; o; o >>= 1) {
        if (tid < o) red[tid] += red[tid + o];
        __syncthreads();
    }
    if (tid == 0) {
        double w = diag ? 1.0 : 2.0;   // symmetry: off-diagonal tiles counted twice
        atomicAdd(&g_S, w * (double)red[0]);
    }
}

// ---------------- K3: broadcast-add the interaction scalar ----------------
__global__ void k_final(float* __restrict__ out) {
    int i = blockIdx.x * 256 + threadIdx.x;       // 128 blocks
    out[i] += (float)g_S;
}

// ---------------- launch ----------------
extern "C" void kernel_launch(void* const* d_in, const int* in_sizes, int n_in,
                              void* d_out, int out_size) {
    const float* x = (const float*)d_in[0];   // [256,128,512]
    const float* W = (const float*)d_in[1];   // [1,512]
    const float* b = (const float*)d_in[2];   // [1]
    const float* V = (const float*)d_in[3];   // [512,512]
    float* out = (float*)d_out;               // [32768,1]

    k_zero <<<64, 256>>>();
    k_prep <<<256 + BN / 16, 256>>>(x, W, b, V, out);
    k_gram <<<NBLK, 256>>>();
    k_final<<<BN / 256, 256>>>(out);
}